// round 16
// baseline (speedup 1.0000x reference)
#include <cuda_runtime.h>
#include <cuda_bf16.h>
#include <cstdint>

#define B_DIM 2048
#define NLEAF 1024

// ---------------- device scratch (no allocations allowed) ----------------
__device__ __align__(256) float g_bufA[(size_t)B_DIM * NLEAF * 32];        // 256 MB
__device__ __align__(256) float g_bufB[(size_t)B_DIM * (NLEAF / 2) * 32];  // 128 MB
// per-MLP weight stage: W1t hi/lo [128][104], W2t hi/lo [128][136], W3t hi/lo [32][136]
#define W1_ELEMS 13312  // 128*104
#define W2_ELEMS 17408  // 128*136
#define W3_ELEMS 4352   // 32*136
#define STAGE_BYTES 140288
__device__ __align__(256) unsigned char g_wstage[2 * STAGE_BYTES];

// ---------------- smem layout (bytes): weights + bias only ----------------
#define OFF_W1H 0
#define OFF_W1L 26624
#define OFF_W2H 53248
#define OFF_W2L 88064
#define OFF_W3H 122880
#define OFF_W3L 131584
#define OFF_BIAS 140288  // b1(128f) b2(128f) b3(32f)
#define SM_BYTES 141440

#define W1_KP 104   // 208B row stride; 208 % 128 = 80 -> conflict-free LDSM
#define W23_KP 136  // 272B row stride; 272 % 128 = 16 -> conflict-free

// ---------------- PTX helpers (base-arch only: ldmatrix + mma.sync) ----------------
__device__ __forceinline__ uint32_t smem_u32(const void* p) {
    uint32_t a;
    asm("{ .reg .u64 t; cvta.to.shared.u64 t, %1; cvt.u32.u64 %0, t; }" : "=r"(a) : "l"(p));
    return a;
}
__device__ __forceinline__ uint4 ldsm4(uint32_t a) {
    uint4 r;
    asm volatile("ldmatrix.sync.aligned.m8n8.x4.shared.b16 {%0,%1,%2,%3}, [%4];"
                 : "=r"(r.x), "=r"(r.y), "=r"(r.z), "=r"(r.w)
                 : "r"(a));
    return r;
}
__device__ __forceinline__ void mma_bf16(float* c, const uint4& a, uint32_t b0, uint32_t b1) {
    asm volatile(
        "mma.sync.aligned.m16n8k16.row.col.f32.bf16.bf16.f32 "
        "{%0,%1,%2,%3}, {%4,%5,%6,%7}, {%8,%9}, {%0,%1,%2,%3};"
        : "+f"(c[0]), "+f"(c[1]), "+f"(c[2]), "+f"(c[3])
        : "r"(a.x), "r"(a.y), "r"(a.z), "r"(a.w), "r"(b0), "r"(b1));
}

// ---------------- bf16 hi/lo split ----------------
__device__ __forceinline__ void split2(float x, float y, uint32_t& h, uint32_t& l) {
    __nv_bfloat16 hx = __float2bfloat16(x), hy = __float2bfloat16(y);
    float rx = x - __bfloat162float(hx), ry = y - __bfloat162float(hy);
    __nv_bfloat16 lx = __float2bfloat16(rx), ly = __float2bfloat16(ry);
    h = (uint32_t)__bfloat16_as_ushort(hx) | ((uint32_t)__bfloat16_as_ushort(hy) << 16);
    l = (uint32_t)__bfloat16_as_ushort(lx) | ((uint32_t)__bfloat16_as_ushort(ly) << 16);
}

__device__ __forceinline__ void copy4(float* dst, const float* __restrict__ src, int nfloats) {
    const float4* s = (const float4*)src;
    float4* d = (float4*)dst;
    int n4 = nfloats >> 2;
    for (int i = threadIdx.x; i < n4; i += blockDim.x) d[i] = s[i];
}

// convert two C tiles (cols 16ks..16ks+15) -> next-layer A fragment (bias+relu+split)
__device__ __forceinline__ void conv2(const float* cA, const float* cB, const float* sBias, int ks,
                                      int cl, uint4& ahi, uint4& alo) {
    float2 b0 = *(const float2*)(sBias + 16 * ks + cl);
    float2 b1 = *(const float2*)(sBias + 16 * ks + 8 + cl);
    float v0 = fmaxf(cA[0] + b0.x, 0.f), v1 = fmaxf(cA[1] + b0.y, 0.f);
    float v2 = fmaxf(cA[2] + b0.x, 0.f), v3 = fmaxf(cA[3] + b0.y, 0.f);
    float u0 = fmaxf(cB[0] + b1.x, 0.f), u1 = fmaxf(cB[1] + b1.y, 0.f);
    float u2 = fmaxf(cB[2] + b1.x, 0.f), u3 = fmaxf(cB[3] + b1.y, 0.f);
    split2(v0, v1, ahi.x, alo.x);
    split2(v2, v3, ahi.y, alo.y);
    split2(u0, u1, ahi.z, alo.z);
    split2(u2, u3, ahi.w, alo.w);
}

// build A fragment from 4 prefetched float2 (row-lo k, row-hi k, row-lo k+8, row-hi k+8)
__device__ __forceinline__ void gfrag_v(float2 p0, float2 p1, float2 p2, float2 p3, uint4& ahi,
                                        uint4& alo) {
    split2(p0.x, p0.y, ahi.x, alo.x);
    split2(p1.x, p1.y, ahi.y, alo.y);
    split2(p2.x, p2.y, ahi.z, alo.z);
    split2(p3.x, p3.y, ahi.w, alo.w);
}

// ---------------- software-pipelined layer ----------------
// Depth-1 pipeline on B LDSMs (static address stream) and on A fragments
// (next ks's conversion runs under current ks's MMAs). Per-accumulator MMA
// order identical to the unpipelined version -> bit-identical results.
template <int NK, int NP2, int WKP, class AGen>
__device__ __forceinline__ void layer_pipe(uint32_t wH, uint32_t wL, AGen agen, float (*c)[4]) {
    uint4 ahi, alo, ahiN, aloN;
    agen(0, ahi, alo);
    uint4 bh = ldsm4(wH);
    uint4 bl = ldsm4(wL);
#pragma unroll
    for (int ks = 0; ks < NK; ks++) {
        if (ks + 1 < NK) agen(ks + 1, ahiN, aloN);
#pragma unroll
        for (int np = 0; np < NP2; np++) {
            const bool last = (ks == NK - 1) && (np == NP2 - 1);
            const int nks = (np == NP2 - 1) ? ks + 1 : ks;
            const int nnp = (np == NP2 - 1) ? 0 : np + 1;
            const uint32_t noff =
                last ? 0u : (uint32_t)(nnp * 16 * (WKP * 2) + nks * 32);
            uint4 bh2 = ldsm4(wH + noff);
            uint4 bl2 = ldsm4(wL + noff);
            float* c0 = c[2 * np];
            float* c1p = c[2 * np + 1];
            mma_bf16(c0, ahi, bh.x, bh.y);
            mma_bf16(c1p, ahi, bh.z, bh.w);
            mma_bf16(c0, ahi, bl.x, bl.y);
            mma_bf16(c1p, ahi, bl.z, bl.w);
            mma_bf16(c0, alo, bh.x, bh.y);
            mma_bf16(c1p, alo, bh.z, bh.w);
            bh = bh2;
            bl = bl2;
        }
        ahi = ahiN;
        alo = aloN;
    }
}

// prefetch one tile's inputs into registers (JOIN: 24 float2, leaf: 8 float2)
template <bool JOIN>
__device__ __forceinline__ void load_inputs(const float* __restrict__ feats,
                                            const float* __restrict__ prev, int off, int nShift,
                                            int tile, int rowIdx, int cl, float2* pf) {
    const int g0 = tile * 128 + rowIdx;
    const int g1 = g0 + 8;
    if (JOIN) {
        const int mask = (1 << nShift) - 1;
        const int b0i = g0 >> nShift, i0 = g0 & mask;
        const int b1i = g1 >> nShift, i1 = g1 & mask;
        const float* f0 = feats + ((size_t)b0i * (NLEAF - 1) + off + i0) * 32;
        const float* f1 = feats + ((size_t)b1i * (NLEAF - 1) + off + i1) * 32;
        const float* cA0 = prev + (((size_t)b0i << (nShift + 1)) + 2 * (size_t)i0) * 32;
        const float* cA1 = prev + (((size_t)b1i << (nShift + 1)) + 2 * (size_t)i1) * 32;
        const float* cB0 = cA0 + 32;
        const float* cB1 = cA1 + 32;
        pf[0] = *(const float2*)(f0 + cl);
        pf[1] = *(const float2*)(f1 + cl);
        pf[2] = *(const float2*)(f0 + cl + 8);
        pf[3] = *(const float2*)(f1 + cl + 8);
        pf[4] = *(const float2*)(f0 + cl + 16);
        pf[5] = *(const float2*)(f1 + cl + 16);
        pf[6] = *(const float2*)(f0 + cl + 24);
        pf[7] = *(const float2*)(f1 + cl + 24);
        pf[8] = *(const float2*)(cA0 + cl);
        pf[9] = *(const float2*)(cA1 + cl);
        pf[10] = *(const float2*)(cA0 + cl + 8);
        pf[11] = *(const float2*)(cA1 + cl + 8);
        pf[12] = *(const float2*)(cA0 + cl + 16);
        pf[13] = *(const float2*)(cA1 + cl + 16);
        pf[14] = *(const float2*)(cA0 + cl + 24);
        pf[15] = *(const float2*)(cA1 + cl + 24);
        pf[16] = *(const float2*)(cB0 + cl);
        pf[17] = *(const float2*)(cB1 + cl);
        pf[18] = *(const float2*)(cB0 + cl + 8);
        pf[19] = *(const float2*)(cB1 + cl + 8);
        pf[20] = *(const float2*)(cB0 + cl + 16);
        pf[21] = *(const float2*)(cB1 + cl + 16);
        pf[22] = *(const float2*)(cB0 + cl + 24);
        pf[23] = *(const float2*)(cB1 + cl + 24);
    } else {
        const float* f0 = feats + (size_t)g0 * 32;
        const float* f1 = feats + (size_t)g1 * 32;
        pf[0] = *(const float2*)(f0 + cl);
        pf[1] = *(const float2*)(f1 + cl);
        pf[2] = *(const float2*)(f0 + cl + 8);
        pf[3] = *(const float2*)(f1 + cl + 8);
        pf[4] = *(const float2*)(f0 + cl + 16);
        pf[5] = *(const float2*)(f1 + cl + 16);
        pf[6] = *(const float2*)(f0 + cl + 24);
        pf[7] = *(const float2*)(f1 + cl + 24);
    }
}

// ---------------- weight prep: transpose [k][n]->[n][k], split hi/lo, pad ----------------
__global__ void prep_weights(const float* __restrict__ sW1, const float* __restrict__ sW2,
                             const float* __restrict__ sW3, const float* __restrict__ jW1,
                             const float* __restrict__ jW2, const float* __restrict__ jW3) {
    int idx = blockIdx.x * blockDim.x + threadIdx.x;
    if (idx >= W1_ELEMS + W2_ELEMS + W3_ELEMS) return;
    int mlp = blockIdx.y;
    const float* W;
    int n, k, Kp, Kreal, N, hiE, loE;
    if (idx < W1_ELEMS) {
        Kp = W1_KP; n = idx / Kp; k = idx % Kp; N = 128;
        Kreal = mlp ? 96 : 32;
        W = mlp ? jW1 : sW1;
        hiE = 0; loE = W1_ELEMS;
    } else if (idx < W1_ELEMS + W2_ELEMS) {
        int li = idx - W1_ELEMS;
        Kp = W23_KP; n = li / Kp; k = li % Kp; N = 128;
        Kreal = 128;
        W = mlp ? jW2 : sW2;
        hiE = 2 * W1_ELEMS; loE = 2 * W1_ELEMS + W2_ELEMS;
    } else {
        int li = idx - W1_ELEMS - W2_ELEMS;
        Kp = W23_KP; n = li / Kp; k = li % Kp; N = 32;
        Kreal = 128;
        W = mlp ? jW3 : sW3;
        hiE = 2 * W1_ELEMS + 2 * W2_ELEMS; loE = hiE + W3_ELEMS;
    }
    float w = (k < Kreal) ? W[k * N + n] : 0.f;
    __nv_bfloat16 bh = __float2bfloat16(w);
    float r = w - __bfloat162float(bh);
    __nv_bfloat16 bl = __float2bfloat16(r);
    __nv_bfloat16* base = (__nv_bfloat16*)(g_wstage + (size_t)mlp * STAGE_BYTES);
    base[hiE + n * Kp + k] = bh;
    base[loE + n * Kp + k] = bl;
}

// ---------------- main kernel: 8 warps x 16 rows, zero barriers, full pipelining ----------------
template <bool JOIN>
__global__ void __launch_bounds__(256, 1)
    mlp3_kernel(const float* __restrict__ feats, int off, int nShift, const float* __restrict__ prev,
                const float* __restrict__ b1, const float* __restrict__ b2,
                const float* __restrict__ b3, float* __restrict__ Y, int numTiles, int mlpIdx) {
    extern __shared__ char sm[];
    float* smF = (float*)sm;
    copy4(smF, (const float*)(g_wstage + (size_t)mlpIdx * STAGE_BYTES), STAGE_BYTES / 4);
    copy4(smF + OFF_BIAS / 4, b1, 128);
    copy4(smF + OFF_BIAS / 4 + 128, b2, 128);
    copy4(smF + OFF_BIAS / 4 + 256, b3, 32);
    __syncthreads();

    const uint32_t su = smem_u32(sm);
    const float* sB1 = smF + OFF_BIAS / 4;
    const float* sB2 = sB1 + 128;
    const float* sB3 = sB2 + 128;

    const int t = threadIdx.x;
    const int w = t >> 5;
    const int lane = t & 31;
    const int cl = (lane & 3) * 2;
    const int rowIdx = w * 16 + (lane >> 2);

    const uint32_t wo1 = (uint32_t)((lane & 7) + ((lane >> 4) << 3)) * (W1_KP * 2) +
                         (uint32_t)(((lane >> 3) & 1) << 4);
    const uint32_t wo23 = (uint32_t)((lane & 7) + ((lane >> 4) << 3)) * (W23_KP * 2) +
                          (uint32_t)(((lane >> 3) & 1) << 4);
    const uint32_t wH1 = su + OFF_W1H + wo1, wL1 = su + OFF_W1L + wo1;
    const uint32_t wH2 = su + OFF_W2H + wo23, wL2 = su + OFF_W2L + wo23;
    const uint32_t wH3 = su + OFF_W3H + wo23, wL3 = su + OFF_W3L + wo23;

    float2 pf[JOIN ? 24 : 8];
    int tile = blockIdx.x;
    if (tile < numTiles) load_inputs<JOIN>(feats, prev, off, nShift, tile, rowIdx, cl, pf);

    for (; tile < numTiles; tile += gridDim.x) {
        const int g0 = tile * 128 + rowIdx;
        const int g1 = g0 + 8;

        float c1[16][4];
#pragma unroll
        for (int i = 0; i < 16; i++)
#pragma unroll
            for (int j = 0; j < 4; j++) c1[i][j] = 0.f;

        // ---- layer 1 from prefetched registers (pipelined) ----
        auto agen1 = [&](int ks, uint4& ahi, uint4& alo) {
            gfrag_v(pf[4 * ks], pf[4 * ks + 1], pf[4 * ks + 2], pf[4 * ks + 3], ahi, alo);
        };
        if (JOIN)
            layer_pipe<6, 8, W1_KP>(wH1, wL1, agen1, c1);
        else
            layer_pipe<2, 8, W1_KP>(wH1, wL1, agen1, c1);

        // ---- prefetch next tile's inputs (covered by layers 2+3) ----
        {
            int nt = tile + gridDim.x;
            int pt = (nt < numTiles) ? nt : tile;
            load_inputs<JOIN>(feats, prev, off, nShift, pt, rowIdx, cl, pf);
        }

        // ---- layer 2: A from c1 registers (pipelined) ----
        float c2[16][4];
#pragma unroll
        for (int i = 0; i < 16; i++)
#pragma unroll
            for (int j = 0; j < 4; j++) c2[i][j] = 0.f;
        auto agen2 = [&](int ks, uint4& ahi, uint4& alo) {
            conv2(c1[2 * ks], c1[2 * ks + 1], sB1, ks, cl, ahi, alo);
        };
        layer_pipe<8, 8, W23_KP>(wH2, wL2, agen2, c2);

        // ---- layer 3 (N=32): A from c2 registers (pipelined) ----
        float c3[4][4];
#pragma unroll
        for (int i = 0; i < 4; i++)
#pragma unroll
            for (int j = 0; j < 4; j++) c3[i][j] = 0.f;
        auto agen3 = [&](int ks, uint4& ahi, uint4& alo) {
            conv2(c2[2 * ks], c2[2 * ks + 1], sB2, ks, cl, ahi, alo);
        };
        layer_pipe<8, 2, W23_KP>(wH3, wL3, agen3, c3);

        // ---- output: bias3, no relu ----
        float* o0 = Y + (size_t)g0 * 32;
        float* o1 = Y + (size_t)g1 * 32;
#pragma unroll
        for (int nt = 0; nt < 4; nt++) {
            float2 bb = *(const float2*)(sB3 + nt * 8 + cl);
            *(float2*)(o0 + nt * 8 + cl) = make_float2(c3[nt][0] + bb.x, c3[nt][1] + bb.y);
            *(float2*)(o1 + nt * 8 + cl) = make_float2(c3[nt][2] + bb.x, c3[nt][3] + bb.y);
        }
    }
}

__global__ void gather_kernel(const float* __restrict__ src, float* __restrict__ out) {
    int b = blockIdx.x * blockDim.x + threadIdx.x;
    if (b < B_DIM) out[b] = src[(size_t)b * 32];
}

extern "C" void kernel_launch(void* const* d_in, const int* in_sizes, int n_in, void* d_out,
                              int out_size) {
    const float* leaf = (const float*)d_in[0];
    const float* internal = (const float*)d_in[1];
    const float* sW1 = (const float*)d_in[2];
    const float* sb1 = (const float*)d_in[3];
    const float* sW2 = (const float*)d_in[4];
    const float* sb2 = (const float*)d_in[5];
    const float* sW3 = (const float*)d_in[6];
    const float* sb3 = (const float*)d_in[7];
    const float* jW1 = (const float*)d_in[8];
    const float* jb1 = (const float*)d_in[9];
    const float* jW2 = (const float*)d_in[10];
    const float* jb2 = (const float*)d_in[11];
    const float* jW3 = (const float*)d_in[12];
    const float* jb3 = (const float*)d_in[13];
    float* out = (float*)d_out;

    float *bufA, *bufB;
    cudaGetSymbolAddress((void**)&bufA, g_bufA);
    cudaGetSymbolAddress((void**)&bufB, g_bufB);

    cudaFuncSetAttribute(mlp3_kernel<false>, cudaFuncAttributeMaxDynamicSharedMemorySize,
                         SM_BYTES);
    cudaFuncSetAttribute(mlp3_kernel<true>, cudaFuncAttributeMaxDynamicSharedMemorySize,
                         SM_BYTES);

    int sms = 148;
    cudaDeviceGetAttribute(&sms, cudaDevAttrMultiProcessorCount, 0);

    const int totalW = W1_ELEMS + W2_ELEMS + W3_ELEMS;
    prep_weights<<<dim3((totalW + 255) / 256, 2), 256>>>(sW1, sW2, sW3, jW1, jW2, jW3);

    // leaf: 2048*1024 rows / 128 = 16384 tiles
    mlp3_kernel<false><<<sms, 256, SM_BYTES>>>(leaf, 0, 0, nullptr, sb1, sb2, sb3, bufA, 16384, 0);

    float* src = bufA;
    float* dst = bufB;
    int off = 0;
    for (int sh = 9; sh >= 0; sh--) {
        int n = 1 << sh;
        int tiles = 16 * n;  // 2048*n/128
        mlp3_kernel<true><<<sms, 256, SM_BYTES>>>(internal, off, sh, src, jb1, jb2, jb3, dst,
                                                  tiles, 1);
        off += n;
        float* tmp = src;
        src = dst;
        dst = tmp;
    }
    gather_kernel<<<(B_DIM + 255) / 256, 256>>>(src, out);
}

// round 17
// speedup vs baseline: 1.3770x; 1.3770x over previous
#include <cuda_runtime.h>
#include <cuda_fp16.h>
#include <cstdint>

#define B_DIM 2048
#define NLEAF 1024

// ---------------- device scratch (no allocations allowed) ----------------
__device__ __align__(256) float g_bufA[(size_t)B_DIM * NLEAF * 32];        // 256 MB
__device__ __align__(256) float g_bufB[(size_t)B_DIM * (NLEAF / 2) * 32];  // 128 MB
// per-MLP weight stage (single fp16): W1t [128][104], W2t [128][136], W3t [32][136]
#define W1_ELEMS 13312  // 128*104
#define W2_ELEMS 17408  // 128*136
#define W3_ELEMS 4352   // 32*136
#define STAGE_BYTES 70144  // (13312+17408+4352)*2
__device__ __align__(256) unsigned char g_wstage[2 * STAGE_BYTES];

// ---------------- smem layout (bytes): weights + bias only ----------------
#define OFF_W1 0       // 26624 B
#define OFF_W2 26624   // 34816 B
#define OFF_W3 61440   // 8704 B
#define OFF_BIAS 70144 // b1(128f) b2(128f) b3(32f) = 1152 B
#define SM_BYTES 71296

#define W1_KP 104   // 208B row stride; 208 % 128 = 80 -> conflict-free LDSM
#define W23_KP 136  // 272B row stride; 272 % 128 = 16 -> conflict-free

// ---------------- PTX helpers (base-arch only: ldmatrix + mma.sync) ----------------
__device__ __forceinline__ uint32_t smem_u32(const void* p) {
    uint32_t a;
    asm("{ .reg .u64 t; cvta.to.shared.u64 t, %1; cvt.u32.u64 %0, t; }" : "=r"(a) : "l"(p));
    return a;
}
__device__ __forceinline__ uint4 ldsm4(uint32_t a) {
    uint4 r;
    asm volatile("ldmatrix.sync.aligned.m8n8.x4.shared.b16 {%0,%1,%2,%3}, [%4];"
                 : "=r"(r.x), "=r"(r.y), "=r"(r.z), "=r"(r.w)
                 : "r"(a));
    return r;
}
__device__ __forceinline__ void mma_f16(float* c, const uint4& a, uint32_t b0, uint32_t b1) {
    asm volatile(
        "mma.sync.aligned.m16n8k16.row.col.f32.f16.f16.f32 "
        "{%0,%1,%2,%3}, {%4,%5,%6,%7}, {%8,%9}, {%0,%1,%2,%3};"
        : "+f"(c[0]), "+f"(c[1]), "+f"(c[2]), "+f"(c[3])
        : "r"(a.x), "r"(a.y), "r"(a.z), "r"(a.w), "r"(b0), "r"(b1));
}

// ---------------- fp16 hi/lo split (A operand; ~2^-22 combined accuracy) ----------------
__device__ __forceinline__ void split2h(float x, float y, uint32_t& h, uint32_t& l) {
    __half hx = __float2half(x), hy = __float2half(y);
    float rx = x - __half2float(hx), ry = y - __half2float(hy);
    __half lx = __float2half(rx), ly = __float2half(ry);
    h = (uint32_t)__half_as_ushort(hx) | ((uint32_t)__half_as_ushort(hy) << 16);
    l = (uint32_t)__half_as_ushort(lx) | ((uint32_t)__half_as_ushort(ly) << 16);
}

__device__ __forceinline__ void copy4(float* dst, const float* __restrict__ src, int nfloats) {
    const float4* s = (const float4*)src;
    float4* d = (float4*)dst;
    int n4 = nfloats >> 2;
    for (int i = threadIdx.x; i < n4; i += blockDim.x) d[i] = s[i];
}

// ---------------- W block: one k-step across NP2*2 n-tiles ----------------
// W single fp16 -> 1 LDSM + 4 MMAs per np-block (was 2 LDSM + 6 MMAs).
template <int NP2, int WKP>
__device__ __forceinline__ void wblock(uint32_t wW, uint32_t ka, const uint4 ahi, const uint4 alo,
                                       float (*c)[4]) {
#pragma unroll
    for (int np = 0; np < NP2; np++) {
        uint4 bh = ldsm4(wW + (uint32_t)np * 16 * (WKP * 2) + ka);
        float* c0 = c[2 * np];
        float* c1p = c[2 * np + 1];
        mma_f16(c0, ahi, bh.x, bh.y);
        mma_f16(c1p, ahi, bh.z, bh.w);
        mma_f16(c0, alo, bh.x, bh.y);
        mma_f16(c1p, alo, bh.z, bh.w);
    }
}

// convert two C tiles (cols 16ks..16ks+15) -> next-layer A fragment (bias+relu+split)
__device__ __forceinline__ void conv2(const float* cA, const float* cB, const float* sBias, int ks,
                                      int cl, uint4& ahi, uint4& alo) {
    float2 b0 = *(const float2*)(sBias + 16 * ks + cl);
    float2 b1 = *(const float2*)(sBias + 16 * ks + 8 + cl);
    float v0 = fmaxf(cA[0] + b0.x, 0.f), v1 = fmaxf(cA[1] + b0.y, 0.f);
    float v2 = fmaxf(cA[2] + b0.x, 0.f), v3 = fmaxf(cA[3] + b0.y, 0.f);
    float u0 = fmaxf(cB[0] + b1.x, 0.f), u1 = fmaxf(cB[1] + b1.y, 0.f);
    float u2 = fmaxf(cB[2] + b1.x, 0.f), u3 = fmaxf(cB[3] + b1.y, 0.f);
    split2h(v0, v1, ahi.x, alo.x);
    split2h(v2, v3, ahi.y, alo.y);
    split2h(u0, u1, ahi.z, alo.z);
    split2h(u2, u3, ahi.w, alo.w);
}

// build A fragment from 4 prefetched float2 (row-lo k, row-hi k, row-lo k+8, row-hi k+8)
__device__ __forceinline__ void gfrag_v(float2 p0, float2 p1, float2 p2, float2 p3, uint4& ahi,
                                        uint4& alo) {
    split2h(p0.x, p0.y, ahi.x, alo.x);
    split2h(p1.x, p1.y, ahi.y, alo.y);
    split2h(p2.x, p2.y, ahi.z, alo.z);
    split2h(p3.x, p3.y, ahi.w, alo.w);
}

// prefetch one tile's inputs into registers (JOIN: 24 float2, leaf: 8 float2)
template <bool JOIN>
__device__ __forceinline__ void load_inputs(const float* __restrict__ feats,
                                            const float* __restrict__ prev, int off, int nShift,
                                            int tile, int rowIdx, int cl, float2* pf) {
    const int g0 = tile * 128 + rowIdx;
    const int g1 = g0 + 8;
    if (JOIN) {
        const int mask = (1 << nShift) - 1;
        const int b0i = g0 >> nShift, i0 = g0 & mask;
        const int b1i = g1 >> nShift, i1 = g1 & mask;
        const float* f0 = feats + ((size_t)b0i * (NLEAF - 1) + off + i0) * 32;
        const float* f1 = feats + ((size_t)b1i * (NLEAF - 1) + off + i1) * 32;
        const float* cA0 = prev + (((size_t)b0i << (nShift + 1)) + 2 * (size_t)i0) * 32;
        const float* cA1 = prev + (((size_t)b1i << (nShift + 1)) + 2 * (size_t)i1) * 32;
        const float* cB0 = cA0 + 32;
        const float* cB1 = cA1 + 32;
        pf[0] = *(const float2*)(f0 + cl);
        pf[1] = *(const float2*)(f1 + cl);
        pf[2] = *(const float2*)(f0 + cl + 8);
        pf[3] = *(const float2*)(f1 + cl + 8);
        pf[4] = *(const float2*)(f0 + cl + 16);
        pf[5] = *(const float2*)(f1 + cl + 16);
        pf[6] = *(const float2*)(f0 + cl + 24);
        pf[7] = *(const float2*)(f1 + cl + 24);
        pf[8] = *(const float2*)(cA0 + cl);
        pf[9] = *(const float2*)(cA1 + cl);
        pf[10] = *(const float2*)(cA0 + cl + 8);
        pf[11] = *(const float2*)(cA1 + cl + 8);
        pf[12] = *(const float2*)(cA0 + cl + 16);
        pf[13] = *(const float2*)(cA1 + cl + 16);
        pf[14] = *(const float2*)(cA0 + cl + 24);
        pf[15] = *(const float2*)(cA1 + cl + 24);
        pf[16] = *(const float2*)(cB0 + cl);
        pf[17] = *(const float2*)(cB1 + cl);
        pf[18] = *(const float2*)(cB0 + cl + 8);
        pf[19] = *(const float2*)(cB1 + cl + 8);
        pf[20] = *(const float2*)(cB0 + cl + 16);
        pf[21] = *(const float2*)(cB1 + cl + 16);
        pf[22] = *(const float2*)(cB0 + cl + 24);
        pf[23] = *(const float2*)(cB1 + cl + 24);
    } else {
        const float* f0 = feats + (size_t)g0 * 32;
        const float* f1 = feats + (size_t)g1 * 32;
        pf[0] = *(const float2*)(f0 + cl);
        pf[1] = *(const float2*)(f1 + cl);
        pf[2] = *(const float2*)(f0 + cl + 8);
        pf[3] = *(const float2*)(f1 + cl + 8);
        pf[4] = *(const float2*)(f0 + cl + 16);
        pf[5] = *(const float2*)(f1 + cl + 16);
        pf[6] = *(const float2*)(f0 + cl + 24);
        pf[7] = *(const float2*)(f1 + cl + 24);
    }
}

// ---------------- weight prep: transpose [k][n]->[n][k], single fp16, pad ----------------
__global__ void prep_weights(const float* __restrict__ sW1, const float* __restrict__ sW2,
                             const float* __restrict__ sW3, const float* __restrict__ jW1,
                             const float* __restrict__ jW2, const float* __restrict__ jW3) {
    int idx = blockIdx.x * blockDim.x + threadIdx.x;
    if (idx >= W1_ELEMS + W2_ELEMS + W3_ELEMS) return;
    int mlp = blockIdx.y;
    const float* W;
    int n, k, Kp, Kreal, N, base;
    if (idx < W1_ELEMS) {
        Kp = W1_KP; n = idx / Kp; k = idx % Kp; N = 128;
        Kreal = mlp ? 96 : 32;
        W = mlp ? jW1 : sW1;
        base = 0;
    } else if (idx < W1_ELEMS + W2_ELEMS) {
        int li = idx - W1_ELEMS;
        Kp = W23_KP; n = li / Kp; k = li % Kp; N = 128;
        Kreal = 128;
        W = mlp ? jW2 : sW2;
        base = W1_ELEMS;
    } else {
        int li = idx - W1_ELEMS - W2_ELEMS;
        Kp = W23_KP; n = li / Kp; k = li % Kp; N = 32;
        Kreal = 128;
        W = mlp ? jW3 : sW3;
        base = W1_ELEMS + W2_ELEMS;
    }
    float w = (k < Kreal) ? W[k * N + n] : 0.f;
    __half* dst = (__half*)(g_wstage + (size_t)mlp * STAGE_BYTES);
    dst[base + n * Kp + k] = __float2half(w);
}

// ---------------- main kernel: 8 warps x 16 rows, zero barriers, input prefetch ----------------
template <bool JOIN>
__global__ void __launch_bounds__(256, 1)
    mlp3_kernel(const float* __restrict__ feats, int off, int nShift, const float* __restrict__ prev,
                const float* __restrict__ b1, const float* __restrict__ b2,
                const float* __restrict__ b3, float* __restrict__ Y, int numTiles, int mlpIdx) {
    extern __shared__ char sm[];
    float* smF = (float*)sm;
    copy4(smF, (const float*)(g_wstage + (size_t)mlpIdx * STAGE_BYTES), STAGE_BYTES / 4);
    copy4(smF + OFF_BIAS / 4, b1, 128);
    copy4(smF + OFF_BIAS / 4 + 128, b2, 128);
    copy4(smF + OFF_BIAS / 4 + 256, b3, 32);
    __syncthreads();

    const uint32_t su = smem_u32(sm);
    const float* sB1 = smF + OFF_BIAS / 4;
    const float* sB2 = sB1 + 128;
    const float* sB3 = sB2 + 128;

    const int t = threadIdx.x;
    const int w = t >> 5;
    const int lane = t & 31;
    const int cl = (lane & 3) * 2;
    const int rowIdx = w * 16 + (lane >> 2);

    const uint32_t wo1 = (uint32_t)((lane & 7) + ((lane >> 4) << 3)) * (W1_KP * 2) +
                         (uint32_t)(((lane >> 3) & 1) << 4);
    const uint32_t wo23 = (uint32_t)((lane & 7) + ((lane >> 4) << 3)) * (W23_KP * 2) +
                          (uint32_t)(((lane >> 3) & 1) << 4);
    const uint32_t wW1 = su + OFF_W1 + wo1;
    const uint32_t wW2 = su + OFF_W2 + wo23;
    const uint32_t wW3 = su + OFF_W3 + wo23;

    float2 pf[JOIN ? 24 : 8];
    int tile = blockIdx.x;
    if (tile < numTiles) load_inputs<JOIN>(feats, prev, off, nShift, tile, rowIdx, cl, pf);

    for (; tile < numTiles; tile += gridDim.x) {
        const int g0 = tile * 128 + rowIdx;
        const int g1 = g0 + 8;

        float c1[16][4];
#pragma unroll
        for (int i = 0; i < 16; i++)
#pragma unroll
            for (int j = 0; j < 4; j++) c1[i][j] = 0.f;

        // ---- layer 1 from prefetched registers ----
        {
            uint4 ahi, alo;
            gfrag_v(pf[0], pf[1], pf[2], pf[3], ahi, alo);
            wblock<8, W1_KP>(wW1, 0, ahi, alo, c1);
            gfrag_v(pf[4], pf[5], pf[6], pf[7], ahi, alo);
            wblock<8, W1_KP>(wW1, 32, ahi, alo, c1);
            if (JOIN) {
                gfrag_v(pf[8], pf[9], pf[10], pf[11], ahi, alo);
                wblock<8, W1_KP>(wW1, 64, ahi, alo, c1);
                gfrag_v(pf[12], pf[13], pf[14], pf[15], ahi, alo);
                wblock<8, W1_KP>(wW1, 96, ahi, alo, c1);
                gfrag_v(pf[16], pf[17], pf[18], pf[19], ahi, alo);
                wblock<8, W1_KP>(wW1, 128, ahi, alo, c1);
                gfrag_v(pf[20], pf[21], pf[22], pf[23], ahi, alo);
                wblock<8, W1_KP>(wW1, 160, ahi, alo, c1);
            }
        }

        // ---- prefetch next tile's inputs (covered by layers 2+3) ----
        {
            int nt = tile + gridDim.x;
            int pt = (nt < numTiles) ? nt : tile;
            load_inputs<JOIN>(feats, prev, off, nShift, pt, rowIdx, cl, pf);
        }

        // ---- layer 2: A from c1 registers ----
        float c2[16][4];
#pragma unroll
        for (int i = 0; i < 16; i++)
#pragma unroll
            for (int j = 0; j < 4; j++) c2[i][j] = 0.f;
#pragma unroll
        for (int ks = 0; ks < 8; ks++) {
            uint4 ahi, alo;
            conv2(c1[2 * ks], c1[2 * ks + 1], sB1, ks, cl, ahi, alo);
            wblock<8, W23_KP>(wW2, (uint32_t)ks * 32, ahi, alo, c2);
        }

        // ---- layer 3 (N=32): A from c2 registers ----
        float c3[4][4];
#pragma unroll
        for (int i = 0; i < 4; i++)
#pragma unroll
            for (int j = 0; j < 4; j++) c3[i][j] = 0.f;
#pragma unroll
        for (int ks = 0; ks < 8; ks++) {
            uint4 ahi, alo;
            conv2(c2[2 * ks], c2[2 * ks + 1], sB2, ks, cl, ahi, alo);
            wblock<2, W23_KP>(wW3, (uint32_t)ks * 32, ahi, alo, c3);
        }

        // ---- output: bias3, no relu ----
        float* o0 = Y + (size_t)g0 * 32;
        float* o1 = Y + (size_t)g1 * 32;
#pragma unroll
        for (int nt = 0; nt < 4; nt++) {
            float2 bb = *(const float2*)(sB3 + nt * 8 + cl);
            *(float2*)(o0 + nt * 8 + cl) = make_float2(c3[nt][0] + bb.x, c3[nt][1] + bb.y);
            *(float2*)(o1 + nt * 8 + cl) = make_float2(c3[nt][2] + bb.x, c3[nt][3] + bb.y);
        }
    }
}

__global__ void gather_kernel(const float* __restrict__ src, float* __restrict__ out) {
    int b = blockIdx.x * blockDim.x + threadIdx.x;
    if (b < B_DIM) out[b] = src[(size_t)b * 32];
}

extern "C" void kernel_launch(void* const* d_in, const int* in_sizes, int n_in, void* d_out,
                              int out_size) {
    const float* leaf = (const float*)d_in[0];
    const float* internal = (const float*)d_in[1];
    const float* sW1 = (const float*)d_in[2];
    const float* sb1 = (const float*)d_in[3];
    const float* sW2 = (const float*)d_in[4];
    const float* sb2 = (const float*)d_in[5];
    const float* sW3 = (const float*)d_in[6];
    const float* sb3 = (const float*)d_in[7];
    const float* jW1 = (const float*)d_in[8];
    const float* jb1 = (const float*)d_in[9];
    const float* jW2 = (const float*)d_in[10];
    const float* jb2 = (const float*)d_in[11];
    const float* jW3 = (const float*)d_in[12];
    const float* jb3 = (const float*)d_in[13];
    float* out = (float*)d_out;

    float *bufA, *bufB;
    cudaGetSymbolAddress((void**)&bufA, g_bufA);
    cudaGetSymbolAddress((void**)&bufB, g_bufB);

    cudaFuncSetAttribute(mlp3_kernel<false>, cudaFuncAttributeMaxDynamicSharedMemorySize,
                         SM_BYTES);
    cudaFuncSetAttribute(mlp3_kernel<true>, cudaFuncAttributeMaxDynamicSharedMemorySize,
                         SM_BYTES);

    int sms = 148;
    cudaDeviceGetAttribute(&sms, cudaDevAttrMultiProcessorCount, 0);

    const int totalW = W1_ELEMS + W2_ELEMS + W3_ELEMS;
    prep_weights<<<dim3((totalW + 255) / 256, 2), 256>>>(sW1, sW2, sW3, jW1, jW2, jW3);

    // leaf: 2048*1024 rows / 128 = 16384 tiles
    mlp3_kernel<false><<<sms, 256, SM_BYTES>>>(leaf, 0, 0, nullptr, sb1, sb2, sb3, bufA, 16384, 0);

    float* src = bufA;
    float* dst = bufB;
    int off = 0;
    for (int sh = 9; sh >= 0; sh--) {
        int n = 1 << sh;
        int tiles = 16 * n;  // 2048*n/128
        mlp3_kernel<true><<<sms, 256, SM_BYTES>>>(internal, off, sh, src, jb1, jb2, jb3, dst,
                                                  tiles, 1);
        off += n;
        float* tmp = src;
        src = dst;
        dst = tmp;
    }
    gather_kernel<<<(B_DIM + 255) / 256, 256>>>(src, out);
}